// round 15
// baseline (speedup 1.0000x reference)
#include <cuda_runtime.h>

#define NSEG 2048
#define EPS 1e-6f
#define THREADS 1024
#define NWARPS (THREADS / 32)
#define SMEM_F4 6144   // 96KB float4 stash: covers ~98% of a segment's s-data
#define GRID 304       // persistent: 2 CTAs/SM x 152 SMs

__device__ int g_seg_start[NSEG + 1];
__device__ int g_next_seg;

// Linear boundary scan (coalesced, no dependent-load chains) + reset the
// work-stealing counter (first GRID segments are statically assigned).
__global__ void bounds_scan_kernel(const int* __restrict__ batch, int n) {
    int i = blockIdx.x * blockDim.x + threadIdx.x;
    if (i >= n) return;
    int b1 = batch[i];
    if (i == 0) {
        g_next_seg = GRID;
        for (int g = 0; g <= b1; g++) g_seg_start[g] = 0;
    } else {
        int b0 = batch[i - 1];
        for (int g = b0 + 1; g <= b1; g++) g_seg_start[g] = i;
    }
    if (i == n - 1) {
        for (int g = b1 + 1; g <= NSEG; g++) g_seg_start[g] = n;
    }
}

__device__ __forceinline__ void warp_sum3(float& a, float& b, float& c) {
#pragma unroll
    for (int o = 16; o > 0; o >>= 1) {
        a += __shfl_xor_sync(0xFFFFFFFFu, a, o);
        b += __shfl_xor_sync(0xFFFFFFFFu, b, o);
        c += __shfl_xor_sync(0xFFFFFFFFu, c, o);
    }
}

// Persistent CTAs, 2 x 1024 per SM (the only geometry that keeps full
// thread count AND L2 residency — R11/R13 falsified every alternative).
// Dynamic work stealing with the fetch pipelined into the single
// per-segment barrier; first segment statically assigned (no startup
// atomic/barrier). Per segment: pass 1 reads s (96KB smem stash) + v and
// accumulates; one barrier publishes partials + next seg id; every warp
// redundantly reduces; pass 2 re-reads v from L2 (LIFO) and s from the
// stash, streaming stores.
__global__ void __launch_bounds__(THREADS, 2)
fused_seg_kernel(const float4* __restrict__ s4,
                 const float4* __restrict__ v4,
                 const float4* __restrict__ w4,
                 const float4* __restrict__ b4,
                 float4* __restrict__ outs4,
                 float4* __restrict__ outv4) {
    extern __shared__ float4 s_stash[];          // SMEM_F4 entries
    __shared__ float red[2][3][NWARPS];          // parity double buffer
    __shared__ int sh_seg[2];

    int t = threadIdx.x;
    int warp = t >> 5, lane = t & 31;
    int parity = 0;

    int seg = blockIdx.x;                        // static first segment

    while (seg < NSEG) {
        int start = __ldg(&g_seg_start[seg]);
        int count = __ldg(&g_seg_start[seg + 1]) - start;

        long long sbase = (long long)start * 64;   // float4 index into s
        long long vbase = (long long)start * 96;   // float4 index into v
        int ns4 = count * 64;
        int nv4 = count * 96;
        int stash_n = (ns4 < SMEM_F4) ? ns4 : SMEM_F4;

        // ---- Pass 1: read s (stash) + v, accumulate ----
        float ss = 0.0f, ss2 = 0.0f, sv2 = 0.0f;
#pragma unroll 2
        for (int i = t; i < ns4; i += THREADS) {
            float4 a = s4[sbase + i];
            if (i < SMEM_F4) s_stash[i] = a;
            ss  += a.x + a.y + a.z + a.w;
            ss2 += a.x * a.x + a.y * a.y + a.z * a.z + a.w * a.w;
        }
#pragma unroll 8
        for (int i = t; i < nv4; i += THREADS) {
            float4 a = v4[vbase + i];
            sv2 += a.x * a.x + a.y * a.y + a.z * a.z + a.w * a.w;
        }

        warp_sum3(ss, ss2, sv2);
        if (t == 0) sh_seg[parity ^ 1] = atomicAdd(&g_next_seg, 1);
        if (lane == 0) {
            red[parity][0][warp] = ss;
            red[parity][1][warp] = ss2;
            red[parity][2][warp] = sv2;
        }
        __syncthreads();   // the ONLY barrier per segment

        if (count > 0) {
            // Redundant cross-warp reduce in every warp (lane i = warp i's
            // partial; 32 warps at 1024 threads, so no guard needed).
            float a0 = red[parity][0][lane];
            float a1 = red[parity][1][lane];
            float a2 = red[parity][2][lane];
            warp_sum3(a0, a1, a2);

            float cnt = (float)count;
            float denom_s = cnt * 256.0f;
            float m = a0 / denom_s;
            float var = fmaxf(a1 / denom_s - m * m, EPS);
            float ivr = 1.0f / var;
            float ivm = 1.0f / fmaxf(a2 / (cnt * 128.0f), EPS);

            // ---- Pass 2 (LIFO): v first (L2 hit), then s (smem stash) ----
#pragma unroll 8
            for (int i = t; i < nv4; i += THREADS) {
                long long g = vbase + i;
                float4 a = __ldcs(&v4[g]);
                float4 o;
                o.x = a.x * ivm;
                o.y = a.y * ivm;
                o.z = a.z * ivm;
                o.w = a.w * ivm;
                __stcs(&outv4[g], o);
            }
#pragma unroll 2
            for (int i = t; i < ns4; i += THREADS) {
                long long g = sbase + i;
                float4 a = (i < stash_n) ? s_stash[i] : __ldcs(&s4[g]);
                int cg = i & 63;                 // 64 float4 per node row
                float4 w = __ldg(&w4[cg]);
                float4 b = __ldg(&b4[cg]);
                float4 o;
                o.x = (a.x - m) * ivr * w.x + b.x;
                o.y = (a.y - m) * ivr * w.y + b.y;
                o.z = (a.z - m) * ivr * w.z + b.z;
                o.w = (a.w - m) * ivr * w.w + b.w;
                __stcs(&outs4[g], o);
            }
        }

        seg = sh_seg[parity ^ 1];
        parity ^= 1;
    }
}

extern "C" void kernel_launch(void* const* d_in, const int* in_sizes, int n_in,
                              void* d_out, int out_size) {
    const float* s      = (const float*)d_in[0];
    const float* v      = (const float*)d_in[1];
    const float* weight = (const float*)d_in[2];
    const float* bias   = (const float*)d_in[3];
    const int*   batch  = (const int*)d_in[4];

    int n = in_sizes[4];
    float* out_s = (float*)d_out;
    float* out_v = out_s + (size_t)n * 256;

    bounds_scan_kernel<<<(n + 1023) / 1024, 1024>>>(batch, n);

    const int SMEM_BYTES = SMEM_F4 * 16;   // 96KB -> 2 CTAs/SM + s stash
    cudaFuncSetAttribute(fused_seg_kernel,
                         cudaFuncAttributeMaxDynamicSharedMemorySize, SMEM_BYTES);

    fused_seg_kernel<<<GRID, THREADS, SMEM_BYTES>>>(
        (const float4*)s, (const float4*)v,
        (const float4*)weight, (const float4*)bias,
        (float4*)out_s, (float4*)out_v);
}

// round 16
// speedup vs baseline: 1.0054x; 1.0054x over previous
#include <cuda_runtime.h>

#define NSEG 2048
#define EPS 1e-6f
#define THREADS 1024
#define NWARPS (THREADS / 32)
#define SMEM_F4 6144   // 96KB float4 stash: covers ~98% of a segment's s-data
#define GRID 304       // persistent: 2 CTAs/SM x 152 SMs

__device__ int g_seg_start[NSEG + 1];
__device__ int g_next_seg;

// Linear boundary scan (coalesced, no dependent-load chains) + reset the
// work-stealing counter (first GRID segments are statically assigned).
__global__ void bounds_scan_kernel(const int* __restrict__ batch, int n) {
    int i = blockIdx.x * blockDim.x + threadIdx.x;
    if (i >= n) return;
    int b1 = batch[i];
    if (i == 0) {
        g_next_seg = GRID;
        for (int g = 0; g <= b1; g++) g_seg_start[g] = 0;
    } else {
        int b0 = batch[i - 1];
        for (int g = b0 + 1; g <= b1; g++) g_seg_start[g] = i;
    }
    if (i == n - 1) {
        for (int g = b1 + 1; g <= NSEG; g++) g_seg_start[g] = n;
    }
}

__device__ __forceinline__ void warp_sum3(float& a, float& b, float& c) {
#pragma unroll
    for (int o = 16; o > 0; o >>= 1) {
        a += __shfl_xor_sync(0xFFFFFFFFu, a, o);
        b += __shfl_xor_sync(0xFFFFFFFFu, b, o);
        c += __shfl_xor_sync(0xFFFFFFFFu, c, o);
    }
}

// Persistent CTAs, 2 x 1024 per SM (the only geometry that keeps full
// thread count AND L2 residency — R11/R13 falsified every alternative).
// Dynamic work stealing with the fetch pipelined into the single
// per-segment barrier; first segment statically assigned (no startup
// atomic/barrier). Per segment: pass 1 reads s (96KB smem stash) + v and
// accumulates; one barrier publishes partials + next seg id; every warp
// redundantly reduces; pass 2 re-reads v from L2 (LIFO) and s from the
// stash, streaming stores.
__global__ void __launch_bounds__(THREADS, 2)
fused_seg_kernel(const float4* __restrict__ s4,
                 const float4* __restrict__ v4,
                 const float4* __restrict__ w4,
                 const float4* __restrict__ b4,
                 float4* __restrict__ outs4,
                 float4* __restrict__ outv4) {
    extern __shared__ float4 s_stash[];          // SMEM_F4 entries
    __shared__ float red[2][3][NWARPS];          // parity double buffer
    __shared__ int sh_seg[2];

    int t = threadIdx.x;
    int warp = t >> 5, lane = t & 31;
    int parity = 0;

    int seg = blockIdx.x;                        // static first segment

    while (seg < NSEG) {
        int start = __ldg(&g_seg_start[seg]);
        int count = __ldg(&g_seg_start[seg + 1]) - start;

        long long sbase = (long long)start * 64;   // float4 index into s
        long long vbase = (long long)start * 96;   // float4 index into v
        int ns4 = count * 64;
        int nv4 = count * 96;
        int stash_n = (ns4 < SMEM_F4) ? ns4 : SMEM_F4;

        // ---- Pass 1: read s (stash) + v, accumulate ----
        float ss = 0.0f, ss2 = 0.0f, sv2 = 0.0f;
#pragma unroll 2
        for (int i = t; i < ns4; i += THREADS) {
            float4 a = s4[sbase + i];
            if (i < SMEM_F4) s_stash[i] = a;
            ss  += a.x + a.y + a.z + a.w;
            ss2 += a.x * a.x + a.y * a.y + a.z * a.z + a.w * a.w;
        }
#pragma unroll 8
        for (int i = t; i < nv4; i += THREADS) {
            float4 a = v4[vbase + i];
            sv2 += a.x * a.x + a.y * a.y + a.z * a.z + a.w * a.w;
        }

        warp_sum3(ss, ss2, sv2);
        if (t == 0) sh_seg[parity ^ 1] = atomicAdd(&g_next_seg, 1);
        if (lane == 0) {
            red[parity][0][warp] = ss;
            red[parity][1][warp] = ss2;
            red[parity][2][warp] = sv2;
        }
        __syncthreads();   // the ONLY barrier per segment

        if (count > 0) {
            // Redundant cross-warp reduce in every warp (lane i = warp i's
            // partial; 32 warps at 1024 threads, so no guard needed).
            float a0 = red[parity][0][lane];
            float a1 = red[parity][1][lane];
            float a2 = red[parity][2][lane];
            warp_sum3(a0, a1, a2);

            float cnt = (float)count;
            float denom_s = cnt * 256.0f;
            float m = a0 / denom_s;
            float var = fmaxf(a1 / denom_s - m * m, EPS);
            float ivr = 1.0f / var;
            float ivm = 1.0f / fmaxf(a2 / (cnt * 128.0f), EPS);

            // ---- Pass 2 (LIFO): v first (L2 hit), then s (smem stash) ----
#pragma unroll 8
            for (int i = t; i < nv4; i += THREADS) {
                long long g = vbase + i;
                float4 a = __ldcs(&v4[g]);
                float4 o;
                o.x = a.x * ivm;
                o.y = a.y * ivm;
                o.z = a.z * ivm;
                o.w = a.w * ivm;
                __stcs(&outv4[g], o);
            }
#pragma unroll 2
            for (int i = t; i < ns4; i += THREADS) {
                long long g = sbase + i;
                float4 a = (i < stash_n) ? s_stash[i] : __ldcs(&s4[g]);
                int cg = i & 63;                 // 64 float4 per node row
                float4 w = __ldg(&w4[cg]);
                float4 b = __ldg(&b4[cg]);
                float4 o;
                o.x = (a.x - m) * ivr * w.x + b.x;
                o.y = (a.y - m) * ivr * w.y + b.y;
                o.z = (a.z - m) * ivr * w.z + b.z;
                o.w = (a.w - m) * ivr * w.w + b.w;
                __stcs(&outs4[g], o);
            }
        }

        seg = sh_seg[parity ^ 1];
        parity ^= 1;
    }
}

extern "C" void kernel_launch(void* const* d_in, const int* in_sizes, int n_in,
                              void* d_out, int out_size) {
    const float* s      = (const float*)d_in[0];
    const float* v      = (const float*)d_in[1];
    const float* weight = (const float*)d_in[2];
    const float* bias   = (const float*)d_in[3];
    const int*   batch  = (const int*)d_in[4];

    int n = in_sizes[4];
    float* out_s = (float*)d_out;
    float* out_v = out_s + (size_t)n * 256;

    bounds_scan_kernel<<<(n + 1023) / 1024, 1024>>>(batch, n);

    const int SMEM_BYTES = SMEM_F4 * 16;   // 96KB -> 2 CTAs/SM + s stash
    cudaFuncSetAttribute(fused_seg_kernel,
                         cudaFuncAttributeMaxDynamicSharedMemorySize, SMEM_BYTES);

    fused_seg_kernel<<<GRID, THREADS, SMEM_BYTES>>>(
        (const float4*)s, (const float4*)v,
        (const float4*)weight, (const float4*)bias,
        (float4*)out_s, (float4*)out_v);
}